// round 13
// baseline (speedup 1.0000x reference)
#include <cuda_runtime.h>
#include <cuda_bf16.h>

// CBOW negative-sampling loss — single fused kernel, cp.async-staged gathers.
// Inputs (metadata order):
//   d_in[0] i_emb        float32  (VOCAB+1, 50)
//   d_in[1] o_emb        float32  (VOCAB+1, 50)
//   d_in[2] target_wids  int32    (B,)
//   d_in[3] context_wids int32    (B, 10)
//   d_in[4] neg_wids     int32    (B, 10)
// Output: scalar float32 = -( sum log_sigmoid(pos) + sum log_sigmoid(-neg) )
//
// Theory: prior LDG variants are pinned at ~2.6 TB/s random gather bandwidth
// = 148 SM x ~64 outstanding L1tex lines x 128B / ~400ns (per-SM miss-pool
// cap). cp.async (LDGSTS) completion is tracked in the async pipe with no
// observed depth cap, so staging the 21 row-gathers per warp through SMEM
// multiplies bytes-in-flight per SM by ~30x at identical DRAM traffic.
//
// Each row (200 B, 8B-aligned at idx*200) is copied as its 16B-aligned 224 B
// window (14 lanes x cp.async.cg 16B) — same 7 sectors the misaligned load
// touched, zero extra traffic. SMEM read offset = (byte_base & 8). The
// (VOCAB+1)-row table makes the +24 B window in-bounds for all valid wids.

#define DIM2  25     // 50 floats = 25 float2
#define CTX   10
#define NNEG  10
#define NSLOT 21     // 10 ctx + 1 target + 10 neg
#define ROWB  200u
#define SLOTB 224    // 16B-aligned staging window
#define MAX_BLOCKS 8192

__device__ float        g_partials[MAX_BLOCKS];
__device__ unsigned int g_count = 0;   // module-load init; reset by last block

__device__ __forceinline__ float log_sigmoid(float x) {
    // min(x,0) - log(1 + exp(-|x|)); log arg in (1,2] -> __logf is safe
    return fminf(x, 0.0f) - __logf(1.0f + __expf(-fabsf(x)));
}

__device__ __forceinline__ void cp16(unsigned int dst_smem, const void* src) {
    asm volatile("cp.async.cg.shared.global [%0], [%1], 16;"
                 :: "r"(dst_smem), "l"(src));
}

__device__ __forceinline__ float2 lds64(unsigned int addr) {
    float2 r;
    asm volatile("ld.shared.v2.f32 {%0,%1}, [%2];"
                 : "=f"(r.x), "=f"(r.y) : "r"(addr));
    return r;
}

// Reduce two independent per-lane partials A,B across the warp in 5 shfls.
// Post: lane 0 holds full sum of A; lane 16 holds full sum of B.
__device__ __forceinline__ float pair_reduce(float A, float B, int lane) {
    float x = (lane & 16) ? A : B;
    float y = __shfl_xor_sync(0xFFFFFFFFu, x, 16);
    float v = ((lane & 16) ? B : A) + y;
    v += __shfl_xor_sync(0xFFFFFFFFu, v, 8);
    v += __shfl_xor_sync(0xFFFFFFFFu, v, 4);
    v += __shfl_xor_sync(0xFFFFFFFFu, v, 2);
    v += __shfl_xor_sync(0xFFFFFFFFu, v, 1);
    return v;
}

__global__ void __launch_bounds__(256) cbow_async_kernel(
    const float* __restrict__ i_emb,
    const float* __restrict__ o_emb,
    const int*   __restrict__ target_wids,
    const int*   __restrict__ context_wids,
    const int*   __restrict__ neg_wids,
    float*       __restrict__ out,
    int B)
{
    __shared__ __align__(16) char stage[8][NSLOT * SLOTB];   // 37632 B
    __shared__ float  s_partial[8];
    __shared__ int    s_is_last;
    __shared__ double s_d[8];

    const int warp_global = (blockIdx.x * blockDim.x + threadIdx.x) >> 5;
    const int lane        = threadIdx.x & 31;
    const int warp_local  = threadIdx.x >> 5;

    float loss = 0.0f;   // meaningful only on lanes 0 and 16 until combined

    if (warp_global < B) {
        const char* __restrict__ ib = (const char*)i_emb;
        const char* __restrict__ ob = (const char*)o_emb;
        const int*  __restrict__ cw = context_wids + warp_global * CTX;
        const int*  __restrict__ nw = neg_wids     + warp_global * NNEG;

        // ---- byte offsets (max 199999*200 = 4.0e7 << 2^32) ----
        unsigned int off[NSLOT];
        #pragma unroll
        for (int c = 0; c < CTX; c++)
            off[c] = (unsigned int)__ldg(&cw[c]) * ROWB;
        off[CTX] = (unsigned int)__ldg(&target_wids[warp_global]) * ROWB;
        #pragma unroll
        for (int n = 0; n < NNEG; n++)
            off[CTX + 1 + n] = (unsigned int)__ldg(&nw[n]) * ROWB;

        const unsigned int sb =
            (unsigned int)__cvta_generic_to_shared(stage[warp_local]);

        // ---- stage all 21 rows via cp.async (deep async MLP) ----
        if (lane < 14) {
            const unsigned int lo = lane * 16;
            #pragma unroll
            for (int s = 0; s < NSLOT; s++) {
                const char* t = (s < CTX) ? ib : ob;
                cp16(sb + s * SLOTB + lo, t + (off[s] & ~15u) + lo);
            }
        }
        asm volatile("cp.async.commit_group;");
        asm volatile("cp.async.wait_group 0;");
        __syncwarp();

        float ax = 0.0f, ay = 0.0f;
        float p[NNEG + 1];
        #pragma unroll
        for (int k = 0; k <= NNEG; k++) p[k] = 0.0f;

        if (lane < DIM2) {
            const unsigned int le = lane * 8;
            // ---- sum of context embeddings ----
            #pragma unroll
            for (int c = 0; c < CTX; c++) {
                const float2 e = lds64(sb + c * SLOTB + (off[c] & 8u) + le);
                ax += e.x;  ay += e.y;
            }
            // ---- 11 per-lane score partials ----
            {
                const float2 e = lds64(sb + CTX * SLOTB + (off[CTX] & 8u) + le);
                p[0] = e.x * ax + e.y * ay;
            }
            #pragma unroll
            for (int n = 0; n < NNEG; n++) {
                const int s = CTX + 1 + n;
                const float2 e = lds64(sb + s * SLOTB + (off[s] & 8u) + le);
                p[n + 1] = e.x * ax + e.y * ay;
            }
        }

        const float inv_ctx = 1.0f / CTX;

        // pair 0: (pos, neg0) — mixed signs
        {
            float v = pair_reduce(p[0], p[1], lane);
            if ((lane & 15) == 0) {
                float sc = v * inv_ctx;
                loss += log_sigmoid((lane & 16) ? -sc : sc);
            }
        }
        // pairs (neg1,neg2) (neg3,neg4) (neg5,neg6) (neg7,neg8)
        #pragma unroll
        for (int k = 2; k <= 8; k += 2) {
            float v = pair_reduce(p[k], p[k + 1], lane);
            if ((lane & 15) == 0)
                loss += log_sigmoid(-v * inv_ctx);
        }
        // leftover neg9: plain butterfly, accumulate at lane 0 only
        {
            float v = p[10];
            #pragma unroll
            for (int o = 16; o > 0; o >>= 1)
                v += __shfl_xor_sync(0xFFFFFFFFu, v, o);
            if (lane == 0)
                loss += log_sigmoid(-v * inv_ctx);
        }
    }

    // combine lanes 0 and 16
    loss += __shfl_xor_sync(0xFFFFFFFFu, loss, 16);
    if (lane == 0) s_partial[warp_local] = loss;
    __syncthreads();

    // block partial + last-block ticket
    if (threadIdx.x == 0) {
        float blk = 0.0f;
        #pragma unroll
        for (int i = 0; i < 8; i++) blk += s_partial[i];
        g_partials[blockIdx.x] = blk;
        __threadfence();
        unsigned int old = atomicAdd(&g_count, 1u);
        s_is_last = (old == gridDim.x - 1);
    }
    __syncthreads();

    if (s_is_last) {
        const int nb2 = gridDim.x;
        volatile float* vp = g_partials;   // writers fenced before the ticket
        double acc = 0.0;
        for (int i = threadIdx.x; i < nb2; i += 256)
            acc += (double)vp[i];
        #pragma unroll
        for (int o = 16; o > 0; o >>= 1)
            acc += __shfl_xor_sync(0xFFFFFFFFu, acc, o);
        if ((threadIdx.x & 31) == 0) s_d[threadIdx.x >> 5] = acc;
        __syncthreads();
        if (threadIdx.x == 0) {
            double t = 0.0;
            #pragma unroll
            for (int i = 0; i < 8; i++) t += s_d[i];
            out[0] = (float)(-t);
            g_count = 0;   // reset for next graph replay
        }
    }
}

extern "C" void kernel_launch(void* const* d_in, const int* in_sizes, int n_in,
                              void* d_out, int out_size)
{
    const float* i_emb        = (const float*)d_in[0];
    const float* o_emb        = (const float*)d_in[1];
    const int*   target_wids  = (const int*)d_in[2];
    const int*   context_wids = (const int*)d_in[3];
    const int*   neg_wids     = (const int*)d_in[4];
    float*       out          = (float*)d_out;

    const int B = in_sizes[2];
    const int rows_per_block = 8;           // 8 warps x 1 row
    int blocks = (B + rows_per_block - 1) / rows_per_block;
    if (blocks > MAX_BLOCKS) blocks = MAX_BLOCKS;   // B=16384 -> 2048 blocks

    cbow_async_kernel<<<blocks, 256>>>(i_emb, o_emb, target_wids,
                                       context_wids, neg_wids, out, B);
}